// round 6
// baseline (speedup 1.0000x reference)
#include <cuda_runtime.h>
#include <cuda_bf16.h>
#include <cstdint>

#define NN 50000
#define EE 800000
#define GG 64
#define HH 64
#define NB ((NN + 255) / 256)   // 196 scan blocks

// ---------------- scratch (device globals; no allocation allowed) ----------
__device__ __align__(16) int   g_degin_i[NN];
__device__ __align__(16) int   g_degout_i[NN];
__device__ __align__(16) int   g_rowptr[NN + 1];
__device__ __align__(16) int   g_cursor[NN];
__device__ __align__(16) int   g_blocksum[NB];
__device__ __align__(16) int   g_csr_src[EE];
__device__ __align__(16) float g_norm_src[NN];
__device__ __align__(16) float g_norm_dst[NN];
__device__ __align__(16) float g_hA[NN * HH];     // feature ping buffer
__device__ __align__(16) float g_hB[NN * HH];     // feature pong buffer
__device__ __align__(16) float g_gsum[GG * HH];   // graph pooling sums
__device__ __align__(16) float g_gcnt[GG];

// ---------------- helpers ---------------------------------------------------
__device__ __forceinline__ void red4(float* p, float4 v) {
    asm volatile("red.global.add.v4.f32 [%0], {%1, %2, %3, %4};"
                 :: "l"(p), "f"(v.x), "f"(v.y), "f"(v.z), "f"(v.w) : "memory");
}
__device__ __forceinline__ uint64_t pack2(float lo, float hi) {
    uint64_t r;
    asm("mov.b64 %0, {%1, %2};" : "=l"(r) : "r"(__float_as_int(lo)), "r"(__float_as_int(hi)));
    return r;
}
__device__ __forceinline__ void unpack2(uint64_t v, float& lo, float& hi) {
    int a, b;
    asm("mov.b64 {%0, %1}, %2;" : "=r"(a), "=r"(b) : "l"(v));
    lo = __int_as_float(a); hi = __int_as_float(b);
}
__device__ __forceinline__ void fma2(uint64_t& a, uint64_t x, uint64_t w) {
    asm("fma.rn.f32x2 %0, %1, %2, %0;" : "+l"(a) : "l"(x), "l"(w));
}
__device__ __forceinline__ void lds_v2u64(uint32_t saddr, uint64_t& a, uint64_t& b) {
    asm volatile("ld.shared.v2.b64 {%0, %1}, [%2];" : "=l"(a), "=l"(b) : "r"(saddr));
}

// ---------------- CSR build --------------------------------------------------
__global__ void init_kernel() {
    int i = blockIdx.x * blockDim.x + threadIdx.x;
    if (i < NN) { g_degin_i[i] = 0; g_degout_i[i] = 0; }
    if (i < GG * HH) g_gsum[i] = 0.f;
    if (i < GG) g_gcnt[i] = 0.f;
}

__global__ void deg_kernel(const int* __restrict__ src, const int* __restrict__ dst) {
    int e = blockIdx.x * blockDim.x + threadIdx.x;
    if (e >= EE) return;
    atomicAdd(&g_degin_i[dst[e]], 1);
    atomicAdd(&g_degout_i[src[e]], 1);
}

// per-block exclusive scan of in-degrees; partial rowptr + block totals
__global__ void scanA_kernel() {
    __shared__ int s[256];
    int t = threadIdx.x;
    int n = blockIdx.x * 256 + t;
    int v = (n < NN) ? g_degin_i[n] : 0;
    s[t] = v;
    __syncthreads();
#pragma unroll
    for (int off = 1; off < 256; off <<= 1) {
        int add = (t >= off) ? s[t - off] : 0;
        __syncthreads();
        s[t] += add;
        __syncthreads();
    }
    if (n < NN) g_rowptr[n] = s[t] - v;          // exclusive within block
    if (t == 255) g_blocksum[blockIdx.x] = s[255];
}

// fused: per-block reduce of preceding block sums + rowptr finalize + cursors
// + features/norms (replaces scanB + scanC + feats)
__global__ void scanC_feats_kernel(const int* __restrict__ graph_ids) {
    __shared__ int s_off;
    int b = blockIdx.x, t = threadIdx.x;
    if (t == 0) s_off = 0;
    __syncthreads();
    int v = (t < b && t < NB) ? g_blocksum[t] : 0;
#pragma unroll
    for (int o = 16; o > 0; o >>= 1) v += __shfl_down_sync(0xFFFFFFFF, v, o);
    if ((t & 31) == 0 && v) atomicAdd(&s_off, v);
    __syncthreads();
    int off = s_off;

    int n = b * 256 + t;
    if (b == 0 && t == 0) g_rowptr[NN] = EE;
    if (n >= NN) return;
    int r = g_rowptr[n] + off;
    g_rowptr[n] = r;
    g_cursor[n] = r;

    float di = (float)g_degin_i[n];
    float dout = (float)g_degout_i[n];
    float h1 = di;
    float h2 = (di - 3.f > 0.f) ? 1.f : 0.f;
    float h3 = 3.f / di;
    float h4 = (di - 4.f > 0.f) ? 1.f : 0.f;
    float ns = rsqrtf(fmaxf(dout, 1.f));
    float nd = rsqrtf(fmaxf(di, 1.f));
    g_norm_src[n] = ns;
    g_norm_dst[n] = nd;
    reinterpret_cast<float4*>(g_hA)[n] =
        make_float4(h1 * ns, h2 * ns, h3 * ns, h4 * ns);
    atomicAdd(&g_gcnt[graph_ids[n]], 1.f);
}

__global__ void scatter_kernel(const int* __restrict__ src, const int* __restrict__ dst) {
    int e = blockIdx.x * blockDim.x + threadIdx.x;
    if (e >= EE) return;
    int d = dst[e];
    int pos = atomicAdd(&g_cursor[d], 1);
    g_csr_src[pos] = src[e];
}

// ---------------- layer 1 fused (4-wide gather + 4x64 GEMM) ------------------
// one thread per node: gather float4 sum, then compute all 64 outputs -> g_hB
__global__ void __launch_bounds__(256) layer1_kernel(
        const float* __restrict__ W1, const float* __restrict__ b1) {
    __shared__ float Ws[4 * HH];
    __shared__ float bs[HH];
    int tid = threadIdx.x;
    if (tid < 4 * HH) Ws[tid] = W1[tid];
    if (tid < HH) bs[tid] = b1[tid];
    __syncthreads();

    int n = blockIdx.x * blockDim.x + tid;
    if (n >= NN) return;
    int e0 = g_rowptr[n], e1 = g_rowptr[n + 1];
    const float4* h4 = reinterpret_cast<const float4*>(g_hA);
    const int* __restrict__ csr = g_csr_src;
    float4 acc = make_float4(0.f, 0.f, 0.f, 0.f);
    int e = e0;
    for (; e + 3 < e1; e += 4) {
        float4 v0 = h4[csr[e]];
        float4 v1 = h4[csr[e + 1]];
        float4 v2 = h4[csr[e + 2]];
        float4 v3 = h4[csr[e + 3]];
        acc.x += (v0.x + v1.x) + (v2.x + v3.x);
        acc.y += (v0.y + v1.y) + (v2.y + v3.y);
        acc.z += (v0.z + v1.z) + (v2.z + v3.z);
        acc.w += (v0.w + v1.w) + (v2.w + v3.w);
    }
    for (; e < e1; e++) {
        float4 v = h4[csr[e]];
        acc.x += v.x; acc.y += v.y; acc.z += v.z; acc.w += v.w;
    }
    float nd = g_norm_dst[n];
    float ns = g_norm_src[n];
    float x0 = acc.x * nd, x1 = acc.y * nd, x2 = acc.z * nd, x3 = acc.w * nd;

    float4* outp = reinterpret_cast<float4*>(g_hB + n * HH);
#pragma unroll
    for (int o4 = 0; o4 < 16; o4++) {
        float4 r;
        float* bp = bs + o4 * 4;
        r.x = bp[0]; r.y = bp[1]; r.z = bp[2]; r.w = bp[3];
#pragma unroll
        for (int j = 0; j < 4; j++) {
            float xj = (j == 0) ? x0 : (j == 1) ? x1 : (j == 2) ? x2 : x3;
            const float* wp = Ws + j * HH + o4 * 4;
            r.x = fmaf(xj, wp[0], r.x);
            r.y = fmaf(xj, wp[1], r.y);
            r.z = fmaf(xj, wp[2], r.z);
            r.w = fmaf(xj, wp[3], r.w);
        }
        r.x = fmaxf(r.x, 0.f) * ns;
        r.y = fmaxf(r.y, 0.f) * ns;
        r.z = fmaxf(r.z, 0.f) * ns;
        r.w = fmaxf(r.w, 0.f) * ns;
        outp[o4] = r;
    }
}

// ---------------- fused layers 2..4 ------------------------------------------
// One warp = 2 nodes; 16 lanes per node, each lane owns one float4 slice.
// Gather (unroll 8/4/1), stage via warp-private smem, GEMM with fma.rn.f32x2.
template <bool LAST>
__global__ void __launch_bounds__(256) layer_kernel(
        const float* __restrict__ hin, float* __restrict__ hout,
        const float* __restrict__ W, const float* __restrict__ b,
        const int* __restrict__ graph_ids) {
    __shared__ __align__(16) float Ws[HH * HH];
    __shared__ __align__(16) float bs[HH];
    __shared__ __align__(16) float xs[8][2][68];   // [warp][node-in-warp][64+pad]

    int tid = threadIdx.x;
    float4* Ws4 = reinterpret_cast<float4*>(Ws);
    const float4* Wg4 = reinterpret_cast<const float4*>(W);
    for (int i = tid; i < HH * HH / 4; i += 256) Ws4[i] = Wg4[i];
    if (tid < HH) bs[tid] = b[tid];
    __syncthreads();

    int warp = tid >> 5;
    int lane = tid & 31;
    int half = lane >> 4;      // node within warp
    int o4 = lane & 15;        // float4 slice

    // bias accumulator init (hoisted)
    uint64_t bi01, bi23;
    {
        float4 bb = reinterpret_cast<float4*>(bs)[o4];
        bi01 = pack2(bb.x, bb.y);
        bi23 = pack2(bb.z, bb.w);
    }
    uint32_t ws_base = (uint32_t)__cvta_generic_to_shared(Ws) + o4 * 16;
    uint32_t xs_base = (uint32_t)__cvta_generic_to_shared(&xs[warp][half][0]);

    const float4* h4 = reinterpret_cast<const float4*>(hin);
    const int* __restrict__ csr = g_csr_src;

    for (int pair = blockIdx.x * 8 + warp; pair * 2 < NN; pair += gridDim.x * 8) {
        int n = pair * 2 + half;
        float4 acc = make_float4(0.f, 0.f, 0.f, 0.f);
        {
            int e0 = g_rowptr[n], e1 = g_rowptr[n + 1];
            int e = e0;
            for (; e + 7 < e1; e += 8) {
                int s0 = csr[e],     s1 = csr[e + 1], s2 = csr[e + 2], s3 = csr[e + 3];
                int s4 = csr[e + 4], s5 = csr[e + 5], s6 = csr[e + 6], s7 = csr[e + 7];
                float4 v0 = h4[s0 * 16 + o4];
                float4 v1 = h4[s1 * 16 + o4];
                float4 v2 = h4[s2 * 16 + o4];
                float4 v3 = h4[s3 * 16 + o4];
                float4 v4 = h4[s4 * 16 + o4];
                float4 v5 = h4[s5 * 16 + o4];
                float4 v6 = h4[s6 * 16 + o4];
                float4 v7 = h4[s7 * 16 + o4];
                acc.x += ((v0.x + v1.x) + (v2.x + v3.x)) + ((v4.x + v5.x) + (v6.x + v7.x));
                acc.y += ((v0.y + v1.y) + (v2.y + v3.y)) + ((v4.y + v5.y) + (v6.y + v7.y));
                acc.z += ((v0.z + v1.z) + (v2.z + v3.z)) + ((v4.z + v5.z) + (v6.z + v7.z));
                acc.w += ((v0.w + v1.w) + (v2.w + v3.w)) + ((v4.w + v5.w) + (v6.w + v7.w));
            }
            for (; e + 3 < e1; e += 4) {
                int s0 = csr[e], s1 = csr[e + 1], s2 = csr[e + 2], s3 = csr[e + 3];
                float4 v0 = h4[s0 * 16 + o4];
                float4 v1 = h4[s1 * 16 + o4];
                float4 v2 = h4[s2 * 16 + o4];
                float4 v3 = h4[s3 * 16 + o4];
                acc.x += (v0.x + v1.x) + (v2.x + v3.x);
                acc.y += (v0.y + v1.y) + (v2.y + v3.y);
                acc.z += (v0.z + v1.z) + (v2.z + v3.z);
                acc.w += (v0.w + v1.w) + (v2.w + v3.w);
            }
            for (; e < e1; e++) {
                float4 v = h4[csr[e] * 16 + o4];
                acc.x += v.x; acc.y += v.y; acc.z += v.z; acc.w += v.w;
            }
            float nd = g_norm_dst[n];
            acc.x *= nd; acc.y *= nd; acc.z *= nd; acc.w *= nd;
            reinterpret_cast<float4*>(&xs[warp][half][0])[o4] = acc;
        }
        __syncwarp();
        {
            uint64_t a01 = bi01, a23 = bi23;
#pragma unroll
            for (int kk = 0; kk < 16; kk++) {
                float4 xv;
                asm volatile("ld.shared.v4.b32 {%0, %1, %2, %3}, [%4];"
                             : "=f"(xv.x), "=f"(xv.y), "=f"(xv.z), "=f"(xv.w)
                             : "r"(xs_base + kk * 16));
#pragma unroll
                for (int j = 0; j < 4; j++) {
                    float xk = (j == 0) ? xv.x : (j == 1) ? xv.y : (j == 2) ? xv.z : xv.w;
                    uint64_t x2 = pack2(xk, xk);
                    uint64_t w01, w23;
                    lds_v2u64(ws_base + (kk * 4 + j) * 256, w01, w23);
                    fma2(a01, x2, w01);
                    fma2(a23, x2, w23);
                }
            }
            float4 r;
            unpack2(a01, r.x, r.y);
            unpack2(a23, r.z, r.w);
            r.x = fmaxf(r.x, 0.f);
            r.y = fmaxf(r.y, 0.f);
            r.z = fmaxf(r.z, 0.f);
            r.w = fmaxf(r.w, 0.f);
            if (!LAST) {
                float ns = g_norm_src[n];
                r.x *= ns; r.y *= ns; r.z *= ns; r.w *= ns;
                reinterpret_cast<float4*>(hout)[n * 16 + o4] = r;
            } else {
                int g = graph_ids[n];
                red4(&g_gsum[g * HH + o4 * 4], r);
            }
        }
        __syncwarp();
    }
}

// final head: per-graph mean, dot with Wout, + bout, sigmoid
__global__ void out_kernel(const float* __restrict__ Wout, const float* __restrict__ bout,
                           float* __restrict__ out) {
    __shared__ float s[HH];
    int g = blockIdx.x;
    int t = threadIdx.x;
    float inv = 1.f / g_gcnt[g];
    float v = g_gsum[g * HH + t] * inv * Wout[t];
    s[t] = v;
    __syncthreads();
    if (t < 32) {
        float x = s[t] + s[t + 32];
#pragma unroll
        for (int off = 16; off > 0; off >>= 1)
            x += __shfl_xor_sync(0xFFFFFFFF, x, off);
        if (t == 0) out[g] = 1.f / (1.f + expf(-(x + bout[0])));
    }
}

// ---------------- launch -----------------------------------------------------
extern "C" void kernel_launch(void* const* d_in, const int* in_sizes, int n_in,
                              void* d_out, int out_size) {
    const int*   src  = (const int*)d_in[0];
    const int*   dst  = (const int*)d_in[1];
    const int*   gids = (const int*)d_in[2];
    const float* W1   = (const float*)d_in[3];
    const float* b1   = (const float*)d_in[4];
    const float* W2   = (const float*)d_in[5];
    const float* b2   = (const float*)d_in[6];
    const float* W3   = (const float*)d_in[7];
    const float* b3   = (const float*)d_in[8];
    const float* W4   = (const float*)d_in[9];
    const float* b4   = (const float*)d_in[10];
    const float* Wout = (const float*)d_in[11];
    const float* bout = (const float*)d_in[12];
    float* out = (float*)d_out;

    float *hA, *hB;
    cudaGetSymbolAddress((void**)&hA, g_hA);
    cudaGetSymbolAddress((void**)&hB, g_hB);

    const int T = 256;
    const int gridN = (NN + T - 1) / T;
    const int gridE = (EE + T - 1) / T;
    const int gridLayer = 888;   // 6 blocks/SM, grid-stride over node pairs

    // CSR build (once; reused for all 4 layers)
    init_kernel<<<gridN, T>>>();
    deg_kernel<<<gridE, T>>>(src, dst);
    scanA_kernel<<<NB, 256>>>();
    scanC_feats_kernel<<<gridN, T>>>(gids);
    scatter_kernel<<<gridE, T>>>(src, dst);

    // layer 1: hA (4-wide) -> hB (64-wide), fused gather+GEMM
    layer1_kernel<<<gridN, T>>>(W1, b1);

    // layers 2..4 fused, double-buffered: B->A, A->B, B->pool
    layer_kernel<false><<<gridLayer, T>>>(hB, hA, W2, b2, gids);
    layer_kernel<false><<<gridLayer, T>>>(hA, hB, W3, b3, gids);
    layer_kernel<true ><<<gridLayer, T>>>(hB, hA, W4, b4, gids);

    out_kernel<<<GG, HH>>>(Wout, bout, out);
}

// round 7
// speedup vs baseline: 1.3374x; 1.3374x over previous
#include <cuda_runtime.h>
#include <cuda_bf16.h>

#define NN 50000
#define EE 800000
#define GG 64
#define HH 64
#define NB ((NN + 255) / 256)   // 196 scan blocks

// ---------------- scratch (device globals; no allocation allowed) ----------
__device__ __align__(16) int   g_degin_i[NN];
__device__ __align__(16) int   g_degout_i[NN];
__device__ __align__(16) int   g_rowptr[NN + 1];
__device__ __align__(16) int   g_cursor[NN];
__device__ __align__(16) int   g_blocksum[NB];
__device__ __align__(16) int   g_csr_src[EE];
__device__ __align__(16) float g_norm_src[NN];
__device__ __align__(16) float g_norm_dst[NN];
__device__ __align__(16) float g_hA[NN * HH];     // feature ping buffer
__device__ __align__(16) float g_hB[NN * HH];     // feature pong buffer
__device__ __align__(16) float g_agg1[NN * 4];    // layer-1 aggregation (4-wide only)
__device__ __align__(16) float g_gsum[GG * HH];   // graph pooling sums
__device__ __align__(16) float g_gcnt[GG];

// ---------------- helpers ---------------------------------------------------
__device__ __forceinline__ void red4(float* p, float4 v) {
    asm volatile("red.global.add.v4.f32 [%0], {%1, %2, %3, %4};"
                 :: "l"(p), "f"(v.x), "f"(v.y), "f"(v.z), "f"(v.w) : "memory");
}

// ---------------- CSR build --------------------------------------------------
__global__ void init_kernel() {
    int i = blockIdx.x * blockDim.x + threadIdx.x;
    if (i < NN) { g_degin_i[i] = 0; g_degout_i[i] = 0; }
    if (i < GG * HH) g_gsum[i] = 0.f;
    if (i < GG) g_gcnt[i] = 0.f;
}

__global__ void deg_kernel(const int* __restrict__ src, const int* __restrict__ dst) {
    int e = blockIdx.x * blockDim.x + threadIdx.x;
    if (e >= EE) return;
    atomicAdd(&g_degin_i[dst[e]], 1);
    atomicAdd(&g_degout_i[src[e]], 1);
}

// per-block exclusive scan of in-degrees; partial rowptr + block totals
__global__ void scanA_kernel() {
    __shared__ int s[256];
    int t = threadIdx.x;
    int n = blockIdx.x * 256 + t;
    int v = (n < NN) ? g_degin_i[n] : 0;
    s[t] = v;
    __syncthreads();
#pragma unroll
    for (int off = 1; off < 256; off <<= 1) {
        int add = (t >= off) ? s[t - off] : 0;
        __syncthreads();
        s[t] += add;
        __syncthreads();
    }
    if (n < NN) g_rowptr[n] = s[t] - v;          // exclusive within block
    if (t == 255) g_blocksum[blockIdx.x] = s[255];
}

// parallel exclusive scan of the 196 block sums (one 256-thread block)
__global__ void scanB_kernel() {
    __shared__ int s[256];
    int t = threadIdx.x;
    int v = (t < NB) ? g_blocksum[t] : 0;
    s[t] = v;
    __syncthreads();
#pragma unroll
    for (int off = 1; off < 256; off <<= 1) {
        int add = (t >= off) ? s[t - off] : 0;
        __syncthreads();
        s[t] += add;
        __syncthreads();
    }
    if (t < NB) g_blocksum[t] = s[t] - v;        // exclusive
    if (t == 0) g_rowptr[NN] = EE;
}

// add block offsets, init cursors, AND build features/norms (fused)
__global__ void scanC_feats_kernel(const int* __restrict__ graph_ids) {
    int n = blockIdx.x * blockDim.x + threadIdx.x;
    if (n >= NN) return;
    int r = g_rowptr[n] + g_blocksum[n >> 8];
    g_rowptr[n] = r;
    g_cursor[n] = r;

    float di = (float)g_degin_i[n];
    float dout = (float)g_degout_i[n];
    float h1 = di;
    float h2 = (di - 3.f > 0.f) ? 1.f : 0.f;
    float h3 = 3.f / di;
    float h4 = (di - 4.f > 0.f) ? 1.f : 0.f;
    float ns = rsqrtf(fmaxf(dout, 1.f));
    float nd = rsqrtf(fmaxf(di, 1.f));
    g_norm_src[n] = ns;
    g_norm_dst[n] = nd;
    reinterpret_cast<float4*>(g_hA)[n] =
        make_float4(h1 * ns, h2 * ns, h3 * ns, h4 * ns);
    atomicAdd(&g_gcnt[graph_ids[n]], 1.f);
}

__global__ void scatter_kernel(const int* __restrict__ src, const int* __restrict__ dst) {
    int e = blockIdx.x * blockDim.x + threadIdx.x;
    if (e >= EE) return;
    int d = dst[e];
    int pos = atomicAdd(&g_cursor[d], 1);
    g_csr_src[pos] = src[e];
}

// ---------------- layer 1 (4-wide) -------------------------------------------
__global__ void agg1_kernel() {
    int n = blockIdx.x * blockDim.x + threadIdx.x;
    if (n >= NN) return;
    int e0 = g_rowptr[n], e1 = g_rowptr[n + 1];
    const float4* h4 = reinterpret_cast<const float4*>(g_hA);
    float4 acc = make_float4(0.f, 0.f, 0.f, 0.f);
    int e = e0;
    for (; e + 1 < e1; e += 2) {
        float4 v0 = h4[g_csr_src[e]];
        float4 v1 = h4[g_csr_src[e + 1]];
        acc.x += v0.x + v1.x; acc.y += v0.y + v1.y;
        acc.z += v0.z + v1.z; acc.w += v0.w + v1.w;
    }
    if (e < e1) {
        float4 v = h4[g_csr_src[e]];
        acc.x += v.x; acc.y += v.y; acc.z += v.z; acc.w += v.w;
    }
    reinterpret_cast<float4*>(g_agg1)[n] = acc;
}

// writes layer-1 output (pre-scaled by norm_src) into g_hA (64-wide)
__global__ void node_first_kernel(const float* __restrict__ W1, const float* __restrict__ b1) {
    int t = blockIdx.x * blockDim.x + threadIdx.x;
    if (t >= NN * HH) return;
    int n = t >> 6;
    int o = t & 63;
    float nd = g_norm_dst[n];
    float ns = g_norm_src[n];
    float4 x = reinterpret_cast<const float4*>(g_agg1)[n];
    float acc = b1[o];
    acc = fmaf(x.x * nd, W1[0 * HH + o], acc);
    acc = fmaf(x.y * nd, W1[1 * HH + o], acc);
    acc = fmaf(x.z * nd, W1[2 * HH + o], acc);
    acc = fmaf(x.w * nd, W1[3 * HH + o], acc);
    acc = fmaxf(acc, 0.f) * ns;
    g_hA[t] = acc;
}

// ---------------- fused layers 2..4 ------------------------------------------
// One warp = 2 nodes; 16 lanes per node, each lane owns one float4 slice.
// Double-buffered: gather from hin (unroll 8/4/1), write hout.
// LAST pools relu(.) into g_gsum instead of writing hout.
template <bool LAST>
__global__ void __launch_bounds__(256) layer_kernel(
        const float* __restrict__ hin, float* __restrict__ hout,
        const float* __restrict__ W, const float* __restrict__ b,
        const int* __restrict__ graph_ids) {
    __shared__ float Ws[HH * HH];
    __shared__ float bs[HH];
    __shared__ float xs[8][2][68];   // [warp][node-in-warp][64+pad]

    int tid = threadIdx.x;
    float4* Ws4 = reinterpret_cast<float4*>(Ws);
    const float4* Wg4 = reinterpret_cast<const float4*>(W);
    for (int i = tid; i < HH * HH / 4; i += 256) Ws4[i] = Wg4[i];
    if (tid < HH) bs[tid] = b[tid];
    __syncthreads();

    int warp = tid >> 5;
    int lane = tid & 31;
    int half = lane >> 4;      // node within warp
    int o4 = lane & 15;        // float4 slice

    const float4* h4 = reinterpret_cast<const float4*>(hin);
    const int* __restrict__ csr = g_csr_src;

    for (int pair = blockIdx.x * 8 + warp; pair * 2 < NN; pair += gridDim.x * 8) {
        int n = pair * 2 + half;
        float4 acc = make_float4(0.f, 0.f, 0.f, 0.f);
        {
            int e0 = g_rowptr[n], e1 = g_rowptr[n + 1];
            int e = e0;
            for (; e + 7 < e1; e += 8) {
                int s0 = csr[e],     s1 = csr[e + 1], s2 = csr[e + 2], s3 = csr[e + 3];
                int s4 = csr[e + 4], s5 = csr[e + 5], s6 = csr[e + 6], s7 = csr[e + 7];
                float4 v0 = h4[s0 * 16 + o4];
                float4 v1 = h4[s1 * 16 + o4];
                float4 v2 = h4[s2 * 16 + o4];
                float4 v3 = h4[s3 * 16 + o4];
                float4 v4 = h4[s4 * 16 + o4];
                float4 v5 = h4[s5 * 16 + o4];
                float4 v6 = h4[s6 * 16 + o4];
                float4 v7 = h4[s7 * 16 + o4];
                acc.x += ((v0.x + v1.x) + (v2.x + v3.x)) + ((v4.x + v5.x) + (v6.x + v7.x));
                acc.y += ((v0.y + v1.y) + (v2.y + v3.y)) + ((v4.y + v5.y) + (v6.y + v7.y));
                acc.z += ((v0.z + v1.z) + (v2.z + v3.z)) + ((v4.z + v5.z) + (v6.z + v7.z));
                acc.w += ((v0.w + v1.w) + (v2.w + v3.w)) + ((v4.w + v5.w) + (v6.w + v7.w));
            }
            for (; e + 3 < e1; e += 4) {
                int s0 = csr[e], s1 = csr[e + 1], s2 = csr[e + 2], s3 = csr[e + 3];
                float4 v0 = h4[s0 * 16 + o4];
                float4 v1 = h4[s1 * 16 + o4];
                float4 v2 = h4[s2 * 16 + o4];
                float4 v3 = h4[s3 * 16 + o4];
                acc.x += (v0.x + v1.x) + (v2.x + v3.x);
                acc.y += (v0.y + v1.y) + (v2.y + v3.y);
                acc.z += (v0.z + v1.z) + (v2.z + v3.z);
                acc.w += (v0.w + v1.w) + (v2.w + v3.w);
            }
            for (; e < e1; e++) {
                float4 v = h4[csr[e] * 16 + o4];
                acc.x += v.x; acc.y += v.y; acc.z += v.z; acc.w += v.w;
            }
            float nd = g_norm_dst[n];
            acc.x *= nd; acc.y *= nd; acc.z *= nd; acc.w *= nd;
            reinterpret_cast<float4*>(&xs[warp][half][0])[o4] = acc;
        }
        __syncwarp();
        {
            float4 r = reinterpret_cast<float4*>(bs)[o4];
            const float* xrow = &xs[warp][half][0];
#pragma unroll
            for (int k = 0; k < HH; k++) {
                float xk = xrow[k];
                float4 w = Ws4[k * 16 + o4];
                r.x = fmaf(xk, w.x, r.x);
                r.y = fmaf(xk, w.y, r.y);
                r.z = fmaf(xk, w.z, r.z);
                r.w = fmaf(xk, w.w, r.w);
            }
            r.x = fmaxf(r.x, 0.f);
            r.y = fmaxf(r.y, 0.f);
            r.z = fmaxf(r.z, 0.f);
            r.w = fmaxf(r.w, 0.f);
            if (!LAST) {
                float ns = g_norm_src[n];
                r.x *= ns; r.y *= ns; r.z *= ns; r.w *= ns;
                reinterpret_cast<float4*>(hout)[n * 16 + o4] = r;
            } else {
                int g = graph_ids[n];
                red4(&g_gsum[g * HH + o4 * 4], r);
            }
        }
        __syncwarp();
    }
}

// final head: per-graph mean, dot with Wout, + bout, sigmoid
__global__ void out_kernel(const float* __restrict__ Wout, const float* __restrict__ bout,
                           float* __restrict__ out) {
    __shared__ float s[HH];
    int g = blockIdx.x;
    int t = threadIdx.x;
    float inv = 1.f / g_gcnt[g];
    float v = g_gsum[g * HH + t] * inv * Wout[t];
    s[t] = v;
    __syncthreads();
    if (t < 32) {
        float x = s[t] + s[t + 32];
#pragma unroll
        for (int off = 16; off > 0; off >>= 1)
            x += __shfl_xor_sync(0xFFFFFFFF, x, off);
        if (t == 0) out[g] = 1.f / (1.f + expf(-(x + bout[0])));
    }
}

// ---------------- launch -----------------------------------------------------
extern "C" void kernel_launch(void* const* d_in, const int* in_sizes, int n_in,
                              void* d_out, int out_size) {
    const int*   src  = (const int*)d_in[0];
    const int*   dst  = (const int*)d_in[1];
    const int*   gids = (const int*)d_in[2];
    const float* W1   = (const float*)d_in[3];
    const float* b1   = (const float*)d_in[4];
    const float* W2   = (const float*)d_in[5];
    const float* b2   = (const float*)d_in[6];
    const float* W3   = (const float*)d_in[7];
    const float* b3   = (const float*)d_in[8];
    const float* W4   = (const float*)d_in[9];
    const float* b4   = (const float*)d_in[10];
    const float* Wout = (const float*)d_in[11];
    const float* bout = (const float*)d_in[12];
    float* out = (float*)d_out;

    // device-global buffer addresses for ping-pong
    float *hA, *hB;
    cudaGetSymbolAddress((void**)&hA, g_hA);
    cudaGetSymbolAddress((void**)&hB, g_hB);

    const int T = 256;
    const int gridN  = (NN + T - 1) / T;
    const int gridE  = (EE + T - 1) / T;
    const int gridNH = (NN * HH + T - 1) / T;
    const int gridLayer = 1184;   // 8 blocks/SM, grid-stride over node pairs

    // CSR build (once; reused for all 4 layers)
    init_kernel<<<gridN, T>>>();
    deg_kernel<<<gridE, T>>>(src, dst);
    scanA_kernel<<<NB, 256>>>();
    scanB_kernel<<<1, 256>>>();
    scanC_feats_kernel<<<gridN, T>>>(gids);
    scatter_kernel<<<gridE, T>>>(src, dst);

    // layer 1 (4-wide): agg from hA[0:4], output (H-wide) back into hA
    agg1_kernel<<<gridN, T>>>();
    node_first_kernel<<<gridNH, T>>>(W1, b1);

    // layers 2..4 fused, double-buffered: A->B, B->A, A->pool
    layer_kernel<false><<<gridLayer, T>>>(hA, hB, W2, b2, gids);
    layer_kernel<false><<<gridLayer, T>>>(hB, hA, W3, b3, gids);
    layer_kernel<true ><<<gridLayer, T>>>(hA, hB, W4, b4, gids);

    out_kernel<<<GG, HH>>>(Wout, bout, out);
}

// round 8
// speedup vs baseline: 1.6524x; 1.2355x over previous
#include <cuda_runtime.h>
#include <cuda_bf16.h>

#define NN 50000
#define EE 800000
#define GG 64
#define HH 64
#define NB ((NN + 255) / 256)   // 196 scan blocks

// ---------------- scratch (device globals; no allocation allowed) ----------
__device__ __align__(16) int   g_degin_i[NN];
__device__ __align__(16) int   g_degout_i[NN];
__device__ __align__(16) int   g_rowptr[NN + 1];
__device__ __align__(16) int   g_cursor[NN];
__device__ __align__(16) int   g_blocksum[NB];
__device__ __align__(16) int   g_csr_src[EE];
__device__ __align__(16) float g_norm_src[NN];
__device__ __align__(16) float g_norm_dst[NN];
__device__ __align__(16) float g_hA[NN * HH];     // feature ping buffer
__device__ __align__(16) float g_hB[NN * HH];     // feature pong buffer
__device__ __align__(16) float g_agg1[NN * 4];    // layer-1 aggregation (4-wide only)
__device__ __align__(16) float g_gsum[GG * HH];   // graph pooling sums
__device__ __align__(16) float g_gcnt[GG];

// ---------------- helpers ---------------------------------------------------
__device__ __forceinline__ void red4(float* p, float4 v) {
    asm volatile("red.global.add.v4.f32 [%0], {%1, %2, %3, %4};"
                 :: "l"(p), "f"(v.x), "f"(v.y), "f"(v.z), "f"(v.w) : "memory");
}

// ---------------- CSR build --------------------------------------------------
__global__ void init_kernel() {
    int i = blockIdx.x * blockDim.x + threadIdx.x;
    if (i < NN) { g_degin_i[i] = 0; g_degout_i[i] = 0; }
    if (i < GG * HH) g_gsum[i] = 0.f;
    if (i < GG) g_gcnt[i] = 0.f;
}

__global__ void deg_kernel(const int* __restrict__ src, const int* __restrict__ dst) {
    int e = blockIdx.x * blockDim.x + threadIdx.x;
    if (e >= EE) return;
    atomicAdd(&g_degin_i[dst[e]], 1);
    atomicAdd(&g_degout_i[src[e]], 1);
}

// per-block exclusive scan of in-degrees; partial rowptr + block totals
__global__ void scanA_kernel() {
    __shared__ int s[256];
    int t = threadIdx.x;
    int n = blockIdx.x * 256 + t;
    int v = (n < NN) ? g_degin_i[n] : 0;
    s[t] = v;
    __syncthreads();
#pragma unroll
    for (int off = 1; off < 256; off <<= 1) {
        int add = (t >= off) ? s[t - off] : 0;
        __syncthreads();
        s[t] += add;
        __syncthreads();
    }
    if (n < NN) g_rowptr[n] = s[t] - v;          // exclusive within block
    if (t == 255) g_blocksum[blockIdx.x] = s[255];
}

// parallel exclusive scan of the 196 block sums (one 256-thread block)
__global__ void scanB_kernel() {
    __shared__ int s[256];
    int t = threadIdx.x;
    int v = (t < NB) ? g_blocksum[t] : 0;
    s[t] = v;
    __syncthreads();
#pragma unroll
    for (int off = 1; off < 256; off <<= 1) {
        int add = (t >= off) ? s[t - off] : 0;
        __syncthreads();
        s[t] += add;
        __syncthreads();
    }
    if (t < NB) g_blocksum[t] = s[t] - v;        // exclusive
    if (t == 0) g_rowptr[NN] = EE;
}

// add block offsets, init cursors, AND build features/norms (fused)
__global__ void scanC_feats_kernel(const int* __restrict__ graph_ids) {
    int n = blockIdx.x * blockDim.x + threadIdx.x;
    if (n >= NN) return;
    int r = g_rowptr[n] + g_blocksum[n >> 8];
    g_rowptr[n] = r;
    g_cursor[n] = r;

    float di = (float)g_degin_i[n];
    float dout = (float)g_degout_i[n];
    float h1 = di;
    float h2 = (di - 3.f > 0.f) ? 1.f : 0.f;
    float h3 = 3.f / di;
    float h4 = (di - 4.f > 0.f) ? 1.f : 0.f;
    float ns = rsqrtf(fmaxf(dout, 1.f));
    float nd = rsqrtf(fmaxf(di, 1.f));
    g_norm_src[n] = ns;
    g_norm_dst[n] = nd;
    reinterpret_cast<float4*>(g_hA)[n] =
        make_float4(h1 * ns, h2 * ns, h3 * ns, h4 * ns);
    atomicAdd(&g_gcnt[graph_ids[n]], 1.f);
}

__global__ void scatter_kernel(const int* __restrict__ src, const int* __restrict__ dst) {
    int e = blockIdx.x * blockDim.x + threadIdx.x;
    if (e >= EE) return;
    int d = dst[e];
    int pos = atomicAdd(&g_cursor[d], 1);
    g_csr_src[pos] = src[e];
}

// ---------------- layer 1 (4-wide) -------------------------------------------
__global__ void agg1_kernel() {
    int n = blockIdx.x * blockDim.x + threadIdx.x;
    if (n >= NN) return;
    int e0 = g_rowptr[n], e1 = g_rowptr[n + 1];
    const float4* h4 = reinterpret_cast<const float4*>(g_hA);
    float4 acc = make_float4(0.f, 0.f, 0.f, 0.f);
    int e = e0;
    for (; e + 1 < e1; e += 2) {
        float4 v0 = h4[g_csr_src[e]];
        float4 v1 = h4[g_csr_src[e + 1]];
        acc.x += v0.x + v1.x; acc.y += v0.y + v1.y;
        acc.z += v0.z + v1.z; acc.w += v0.w + v1.w;
    }
    if (e < e1) {
        float4 v = h4[g_csr_src[e]];
        acc.x += v.x; acc.y += v.y; acc.z += v.z; acc.w += v.w;
    }
    reinterpret_cast<float4*>(g_agg1)[n] = acc;
}

// writes layer-1 output (pre-scaled by norm_src) into g_hA (64-wide)
__global__ void node_first_kernel(const float* __restrict__ W1, const float* __restrict__ b1) {
    int t = blockIdx.x * blockDim.x + threadIdx.x;
    if (t >= NN * HH) return;
    int n = t >> 6;
    int o = t & 63;
    float nd = g_norm_dst[n];
    float ns = g_norm_src[n];
    float4 x = reinterpret_cast<const float4*>(g_agg1)[n];
    float acc = b1[o];
    acc = fmaf(x.x * nd, W1[0 * HH + o], acc);
    acc = fmaf(x.y * nd, W1[1 * HH + o], acc);
    acc = fmaf(x.z * nd, W1[2 * HH + o], acc);
    acc = fmaf(x.w * nd, W1[3 * HH + o], acc);
    acc = fmaxf(acc, 0.f) * ns;
    g_hA[t] = acc;
}

// ---------------- fused layers 2..4 ------------------------------------------
// One warp = 4 nodes (a "quad"). Gather: each lane does 2 nodes' float4 slice
// (nodes half and half+2). GEMM: each lane computes slice o4 for 2 nodes
// (2*half, 2*half+1) sharing one W load -> halves W SMEM traffic per node.
template <bool LAST>
__global__ void __launch_bounds__(256) layer_kernel(
        const float* __restrict__ hin, float* __restrict__ hout,
        const float* __restrict__ W, const float* __restrict__ b,
        const int* __restrict__ graph_ids) {
    __shared__ float Ws[HH * HH];
    __shared__ float bs[HH];
    __shared__ float xs[8][4][68];   // [warp][node-in-quad][64+pad]

    int tid = threadIdx.x;
    float4* Ws4 = reinterpret_cast<float4*>(Ws);
    const float4* Wg4 = reinterpret_cast<const float4*>(W);
    for (int i = tid; i < HH * HH / 4; i += 256) Ws4[i] = Wg4[i];
    if (tid < HH) bs[tid] = b[tid];
    __syncthreads();

    int warp = tid >> 5;
    int lane = tid & 31;
    int half = lane >> 4;      // 0 or 1
    int o4 = lane & 15;        // float4 slice

    const float4* h4 = reinterpret_cast<const float4*>(hin);
    const int* __restrict__ csr = g_csr_src;

    const int NQ = NN / 4;     // 12500 quads (NN divisible by 4)

    for (int quad = blockIdx.x * 8 + warp; quad < NQ; quad += gridDim.x * 8) {
        // ---- gather: this lane handles nodes (half) and (half+2) of the quad
#pragma unroll
        for (int g = 0; g < 2; g++) {
            int q = half + 2 * g;
            int n = quad * 4 + q;
            int e0 = g_rowptr[n], e1 = g_rowptr[n + 1];
            float4 acc = make_float4(0.f, 0.f, 0.f, 0.f);
            int e = e0;
            for (; e + 3 < e1; e += 4) {
                int s0 = csr[e], s1 = csr[e + 1], s2 = csr[e + 2], s3 = csr[e + 3];
                float4 v0 = h4[s0 * 16 + o4];
                float4 v1 = h4[s1 * 16 + o4];
                float4 v2 = h4[s2 * 16 + o4];
                float4 v3 = h4[s3 * 16 + o4];
                acc.x += (v0.x + v1.x) + (v2.x + v3.x);
                acc.y += (v0.y + v1.y) + (v2.y + v3.y);
                acc.z += (v0.z + v1.z) + (v2.z + v3.z);
                acc.w += (v0.w + v1.w) + (v2.w + v3.w);
            }
            for (; e < e1; e++) {
                float4 v = h4[csr[e] * 16 + o4];
                acc.x += v.x; acc.y += v.y; acc.z += v.z; acc.w += v.w;
            }
            float nd = g_norm_dst[n];
            acc.x *= nd; acc.y *= nd; acc.z *= nd; acc.w *= nd;
            reinterpret_cast<float4*>(&xs[warp][q][0])[o4] = acc;
        }
        __syncwarp();
        // ---- GEMM: this lane computes slice o4 for nodes q0=2*half, q1=2*half+1
        {
            int q0 = 2 * half;
            int n0 = quad * 4 + q0;
            int n1 = n0 + 1;
            float4 bb = reinterpret_cast<float4*>(bs)[o4];
            float4 r0 = bb, r1 = bb;
            const float4* x0row = reinterpret_cast<const float4*>(&xs[warp][q0][0]);
            const float4* x1row = reinterpret_cast<const float4*>(&xs[warp][q0 + 1][0]);
#pragma unroll
            for (int k4 = 0; k4 < 16; k4++) {
                float4 x0v = x0row[k4];
                float4 x1v = x1row[k4];
#pragma unroll
                for (int j = 0; j < 4; j++) {
                    float4 w = Ws4[(k4 * 4 + j) * 16 + o4];
                    float a = (j == 0) ? x0v.x : (j == 1) ? x0v.y : (j == 2) ? x0v.z : x0v.w;
                    float c = (j == 0) ? x1v.x : (j == 1) ? x1v.y : (j == 2) ? x1v.z : x1v.w;
                    r0.x = fmaf(a, w.x, r0.x);
                    r0.y = fmaf(a, w.y, r0.y);
                    r0.z = fmaf(a, w.z, r0.z);
                    r0.w = fmaf(a, w.w, r0.w);
                    r1.x = fmaf(c, w.x, r1.x);
                    r1.y = fmaf(c, w.y, r1.y);
                    r1.z = fmaf(c, w.z, r1.z);
                    r1.w = fmaf(c, w.w, r1.w);
                }
            }
            r0.x = fmaxf(r0.x, 0.f); r0.y = fmaxf(r0.y, 0.f);
            r0.z = fmaxf(r0.z, 0.f); r0.w = fmaxf(r0.w, 0.f);
            r1.x = fmaxf(r1.x, 0.f); r1.y = fmaxf(r1.y, 0.f);
            r1.z = fmaxf(r1.z, 0.f); r1.w = fmaxf(r1.w, 0.f);
            if (!LAST) {
                float ns0 = g_norm_src[n0];
                float ns1 = g_norm_src[n1];
                r0.x *= ns0; r0.y *= ns0; r0.z *= ns0; r0.w *= ns0;
                r1.x *= ns1; r1.y *= ns1; r1.z *= ns1; r1.w *= ns1;
                reinterpret_cast<float4*>(hout)[n0 * 16 + o4] = r0;
                reinterpret_cast<float4*>(hout)[n1 * 16 + o4] = r1;
            } else {
                int g0 = graph_ids[n0];
                int g1 = graph_ids[n1];
                red4(&g_gsum[g0 * HH + o4 * 4], r0);
                red4(&g_gsum[g1 * HH + o4 * 4], r1);
            }
        }
        __syncwarp();
    }
}

// final head: per-graph mean, dot with Wout, + bout, sigmoid
__global__ void out_kernel(const float* __restrict__ Wout, const float* __restrict__ bout,
                           float* __restrict__ out) {
    __shared__ float s[HH];
    int g = blockIdx.x;
    int t = threadIdx.x;
    float inv = 1.f / g_gcnt[g];
    float v = g_gsum[g * HH + t] * inv * Wout[t];
    s[t] = v;
    __syncthreads();
    if (t < 32) {
        float x = s[t] + s[t + 32];
#pragma unroll
        for (int off = 16; off > 0; off >>= 1)
            x += __shfl_xor_sync(0xFFFFFFFF, x, off);
        if (t == 0) out[g] = 1.f / (1.f + expf(-(x + bout[0])));
    }
}

// ---------------- launch -----------------------------------------------------
extern "C" void kernel_launch(void* const* d_in, const int* in_sizes, int n_in,
                              void* d_out, int out_size) {
    const int*   src  = (const int*)d_in[0];
    const int*   dst  = (const int*)d_in[1];
    const int*   gids = (const int*)d_in[2];
    const float* W1   = (const float*)d_in[3];
    const float* b1   = (const float*)d_in[4];
    const float* W2   = (const float*)d_in[5];
    const float* b2   = (const float*)d_in[6];
    const float* W3   = (const float*)d_in[7];
    const float* b3   = (const float*)d_in[8];
    const float* W4   = (const float*)d_in[9];
    const float* b4   = (const float*)d_in[10];
    const float* Wout = (const float*)d_in[11];
    const float* bout = (const float*)d_in[12];
    float* out = (float*)d_out;

    // device-global buffer addresses for ping-pong
    float *hA, *hB;
    cudaGetSymbolAddress((void**)&hA, g_hA);
    cudaGetSymbolAddress((void**)&hB, g_hB);

    const int T = 256;
    const int gridN  = (NN + T - 1) / T;
    const int gridE  = (EE + T - 1) / T;
    const int gridNH = (NN * HH + T - 1) / T;
    const int gridLayer = 888;

    // CSR build (once; reused for all 4 layers)
    init_kernel<<<gridN, T>>>();
    deg_kernel<<<gridE, T>>>(src, dst);
    scanA_kernel<<<NB, 256>>>();
    scanB_kernel<<<1, 256>>>();
    scanC_feats_kernel<<<gridN, T>>>(gids);
    scatter_kernel<<<gridE, T>>>(src, dst);

    // layer 1 (4-wide): agg from hA[0:4], output (H-wide) back into hA
    agg1_kernel<<<gridN, T>>>();
    node_first_kernel<<<gridNH, T>>>(W1, b1);

    // layers 2..4 fused, double-buffered: A->B, B->A, A->pool
    layer_kernel<false><<<gridLayer, T>>>(hA, hB, W2, b2, gids);
    layer_kernel<false><<<gridLayer, T>>>(hB, hA, W3, b3, gids);
    layer_kernel<true ><<<gridLayer, T>>>(hA, hB, W4, b4, gids);

    out_kernel<<<GG, HH>>>(Wout, bout, out);
}